// round 11
// baseline (speedup 1.0000x reference)
#include <cuda_runtime.h>
#include <cuda_fp16.h>

// CompetitiveLayer: 21 x { AF = AT/(1+K@BF); BF = BT/(1+AF@K) }, K = param^2,
// then C = param^2 * AF[:,None] * BF[None,:].
//
// R10 lessons baked in:
//  - __threadfence (CCTL.IVALL) in hot kernels flushes L1 -> banned. No
//    fences, no atomics anywhere; ordering via kernel boundaries only.
//  - Kernels pay ~2us ramp + ~1.5us gap each -> fewer, longer kernels.
//
// This version: ONE kernel per iteration. Each block owns 8 rows; it computes
// AF for those rows (row dot vs BF, local), staging the 8x4096 fp16 K-tile in
// 64KB of shared memory, then computes the column partials for the SAME rows
// from smem — K is read from L2 ONCE per iteration (was twice). Partials go
// to fp16 tmp (4MB); a tiny finalize kernel reduces them in fixed order.
// Iteration 0 folds in the K=param^2 fp16 prep (reads P fp32, writes g_Kh).

#define N        4096
#define NITER    21
#define R        8                 // rows per iteration block
#define NBLK_IT  (N / R)           // 512 blocks
#define NTHR     256

// smem layout: sBF (fp32, 16KB) | tile (fp16, 64KB) | sAFloc (8 floats)
#define SMEM_IT  (N * 4 + R * N * 2 + 64)

// Scratch — __device__ globals (no cudaMalloc allowed)
__device__ __half g_Kh[(size_t)N * N];          // fp16 param^2 (32 MB)
__device__ float  g_AF[N];
__device__ float  g_BF[N];
__device__ __half g_tmph[(size_t)NBLK_IT * N];  // column partials (4 MB)

// ---------------------------------------------------------------------------
// Per-iteration kernel. Block b owns rows [8b, 8b+8).
//   pass 1 (warp per row): AF[i] = AT[i]/(1 + Kh[i,:].BF); tile row -> smem.
//           first==1: read P fp32, square, convert; also persist to g_Kh.
//   pass 2 (thread per 16 cols): tmph[b][j] = sum_{r<8} AF_loc[r]*tile[r][j].
// No cross-block communication inside the kernel.
// ---------------------------------------------------------------------------
__global__ __launch_bounds__(NTHR)
void iter_kernel(const float* __restrict__ P,
                 const float* __restrict__ AT,
                 const float* __restrict__ BT,
                 int first)
{
    extern __shared__ __align__(16) char smem_raw[];
    float*  sBF    = reinterpret_cast<float*>(smem_raw);                 // [N]
    __half* tile   = reinterpret_cast<__half*>(smem_raw + N * 4);        // [R*N]
    float*  sAFloc = reinterpret_cast<float*>(smem_raw + N * 4 + R * N * 2);

    const int tid  = threadIdx.x;
    const int bid  = blockIdx.x;
    const int warp = tid >> 5;
    const int lane = tid & 31;

    // ---- stage BF (fp32) into smem ----
    {
        const float4* src = first ? reinterpret_cast<const float4*>(BT)
                                  : reinterpret_cast<const float4*>(g_BF);
        float4* dst = reinterpret_cast<float4*>(sBF);
        #pragma unroll
        for (int i = tid; i < N / 4; i += NTHR) dst[i] = src[i];
    }
    __syncthreads();

    // ---- pass 1: one row per warp ----
    const int row = bid * R + warp;
    uint4* krow_s = reinterpret_cast<uint4*>(tile + warp * N);
    float acc = 0.f;

    if (first) {
        const float4* prow = reinterpret_cast<const float4*>(P + ((size_t)row << 12));
        uint4* krow_g = reinterpret_cast<uint4*>(g_Kh + ((size_t)row << 12));
        #pragma unroll
        for (int j = lane; j < N / 8; j += 32) {          // 16 trips
            float4 a = prow[2 * j];
            float4 b = prow[2 * j + 1];
            float s0 = a.x * a.x, s1 = a.y * a.y, s2 = a.z * a.z, s3 = a.w * a.w;
            float s4 = b.x * b.x, s5 = b.y * b.y, s6 = b.z * b.z, s7 = b.w * b.w;
            const float* bf = &sBF[j * 8];
            acc = fmaf(s0, bf[0], acc); acc = fmaf(s1, bf[1], acc);
            acc = fmaf(s2, bf[2], acc); acc = fmaf(s3, bf[3], acc);
            acc = fmaf(s4, bf[4], acc); acc = fmaf(s5, bf[5], acc);
            acc = fmaf(s6, bf[6], acc); acc = fmaf(s7, bf[7], acc);
            __half2 h0 = __floats2half2_rn(s0, s1);
            __half2 h1 = __floats2half2_rn(s2, s3);
            __half2 h2 = __floats2half2_rn(s4, s5);
            __half2 h3 = __floats2half2_rn(s6, s7);
            uint4 v;
            v.x = *reinterpret_cast<unsigned*>(&h0);
            v.y = *reinterpret_cast<unsigned*>(&h1);
            v.z = *reinterpret_cast<unsigned*>(&h2);
            v.w = *reinterpret_cast<unsigned*>(&h3);
            krow_s[j] = v;
            __stcg(&krow_g[j], v);    // persist fp16 K for later iterations
        }
    } else {
        const uint4* krow_g = reinterpret_cast<const uint4*>(g_Kh + ((size_t)row << 12));
        #pragma unroll
        for (int j = lane; j < N / 8; j += 32) {          // 16 trips, 16B each
            uint4 v = krow_g[j];
            krow_s[j] = v;
            const float* bf = &sBF[j * 8];
            float2 f0 = __half22float2(*reinterpret_cast<__half2*>(&v.x));
            float2 f1 = __half22float2(*reinterpret_cast<__half2*>(&v.y));
            float2 f2 = __half22float2(*reinterpret_cast<__half2*>(&v.z));
            float2 f3 = __half22float2(*reinterpret_cast<__half2*>(&v.w));
            acc = fmaf(f0.x, bf[0], acc); acc = fmaf(f0.y, bf[1], acc);
            acc = fmaf(f1.x, bf[2], acc); acc = fmaf(f1.y, bf[3], acc);
            acc = fmaf(f2.x, bf[4], acc); acc = fmaf(f2.y, bf[5], acc);
            acc = fmaf(f3.x, bf[6], acc); acc = fmaf(f3.y, bf[7], acc);
        }
    }
    #pragma unroll
    for (int o = 16; o > 0; o >>= 1) acc += __shfl_xor_sync(0xFFFFFFFFu, acc, o);
    if (lane == 0) {
        float af = AT[row] / (1.0f + acc);
        sAFloc[warp] = af;
        __stcg(&g_AF[row], af);       // for later iterations / final C
    }
    __syncthreads();

    // ---- pass 2: column partials from smem tile; thread owns 16 cols ----
    {
        const int j0 = tid * 16;                           // half index
        float accc[16];
        #pragma unroll
        for (int k = 0; k < 16; k++) accc[k] = 0.f;

        #pragma unroll
        for (int r = 0; r < R; r++) {                      // fixed order
            const float a = sAFloc[r];
            uint4 v0 = *reinterpret_cast<const uint4*>(tile + r * N + j0);
            uint4 v1 = *reinterpret_cast<const uint4*>(tile + r * N + j0 + 8);
            float2 f;
            f = __half22float2(*reinterpret_cast<__half2*>(&v0.x));
            accc[0]  = fmaf(a, f.x, accc[0]);  accc[1]  = fmaf(a, f.y, accc[1]);
            f = __half22float2(*reinterpret_cast<__half2*>(&v0.y));
            accc[2]  = fmaf(a, f.x, accc[2]);  accc[3]  = fmaf(a, f.y, accc[3]);
            f = __half22float2(*reinterpret_cast<__half2*>(&v0.z));
            accc[4]  = fmaf(a, f.x, accc[4]);  accc[5]  = fmaf(a, f.y, accc[5]);
            f = __half22float2(*reinterpret_cast<__half2*>(&v0.w));
            accc[6]  = fmaf(a, f.x, accc[6]);  accc[7]  = fmaf(a, f.y, accc[7]);
            f = __half22float2(*reinterpret_cast<__half2*>(&v1.x));
            accc[8]  = fmaf(a, f.x, accc[8]);  accc[9]  = fmaf(a, f.y, accc[9]);
            f = __half22float2(*reinterpret_cast<__half2*>(&v1.y));
            accc[10] = fmaf(a, f.x, accc[10]); accc[11] = fmaf(a, f.y, accc[11]);
            f = __half22float2(*reinterpret_cast<__half2*>(&v1.z));
            accc[12] = fmaf(a, f.x, accc[12]); accc[13] = fmaf(a, f.y, accc[13]);
            f = __half22float2(*reinterpret_cast<__half2*>(&v1.w));
            accc[14] = fmaf(a, f.x, accc[14]); accc[15] = fmaf(a, f.y, accc[15]);
        }

        __half2 h[8];
        #pragma unroll
        for (int k = 0; k < 8; k++)
            h[k] = __floats2half2_rn(accc[2 * k], accc[2 * k + 1]);
        uint4 o0, o1;
        o0.x = *reinterpret_cast<unsigned*>(&h[0]);
        o0.y = *reinterpret_cast<unsigned*>(&h[1]);
        o0.z = *reinterpret_cast<unsigned*>(&h[2]);
        o0.w = *reinterpret_cast<unsigned*>(&h[3]);
        o1.x = *reinterpret_cast<unsigned*>(&h[4]);
        o1.y = *reinterpret_cast<unsigned*>(&h[5]);
        o1.z = *reinterpret_cast<unsigned*>(&h[6]);
        o1.w = *reinterpret_cast<unsigned*>(&h[7]);
        uint4* dst = reinterpret_cast<uint4*>(g_tmph + (size_t)bid * N + j0);
        __stcg(&dst[0], o0);
        __stcg(&dst[1], o1);
    }
}

// ---------------------------------------------------------------------------
// Finalize: BF[j] = BT[j] / (1 + sum_{c<512} tmph[c][j]).
// grid = 8 x 256; each thread owns a column PAIR (one half2 load per chunk).
// 4 accumulators in a fixed interleave -> deterministic.
// ---------------------------------------------------------------------------
__global__ __launch_bounds__(256, 4)
void finalize_bf_kernel(const float* __restrict__ BT)
{
    const int p = blockIdx.x * 256 + threadIdx.x;   // column pair index
    const unsigned* t = reinterpret_cast<const unsigned*>(g_tmph) + p;

    float2 a0 = make_float2(0.f, 0.f), a1 = a0, a2 = a0, a3 = a0;
    #pragma unroll 4
    for (int c = 0; c < NBLK_IT; c += 4) {
        unsigned u0 = __ldcg(t + (size_t)(c + 0) * (N / 2));
        unsigned u1 = __ldcg(t + (size_t)(c + 1) * (N / 2));
        unsigned u2 = __ldcg(t + (size_t)(c + 2) * (N / 2));
        unsigned u3 = __ldcg(t + (size_t)(c + 3) * (N / 2));
        float2 f0 = __half22float2(*reinterpret_cast<__half2*>(&u0));
        float2 f1 = __half22float2(*reinterpret_cast<__half2*>(&u1));
        float2 f2 = __half22float2(*reinterpret_cast<__half2*>(&u2));
        float2 f3 = __half22float2(*reinterpret_cast<__half2*>(&u3));
        a0.x += f0.x; a0.y += f0.y;
        a1.x += f1.x; a1.y += f1.y;
        a2.x += f2.x; a2.y += f2.y;
        a3.x += f3.x; a3.y += f3.y;
    }
    float sx = (a0.x + a1.x) + (a2.x + a3.x);
    float sy = (a0.y + a1.y) + (a2.y + a3.y);

    const float2 bt = reinterpret_cast<const float2*>(BT)[p];
    float2 out;
    out.x = bt.x / (1.0f + sx);
    out.y = bt.y / (1.0f + sy);
    reinterpret_cast<float2*>(g_BF)[p] = out;
}

// ---------------------------------------------------------------------------
// Output: C[i][j] = param[i][j]^2 * AF[i] * BF[j]  — exact fp32 K.
// ---------------------------------------------------------------------------
__global__ __launch_bounds__(256, 4)
void compute_c_kernel(const float* __restrict__ P, float* __restrict__ C)
{
    const size_t idx = (size_t)blockIdx.x * 256 + threadIdx.x;  // float4 index
    const int row  = (int)(idx >> 10);
    const int col4 = (int)(idx & 1023);

    const float a  = g_AF[row];
    const float4 p = reinterpret_cast<const float4*>(P)[idx];
    const float4 b = *reinterpret_cast<const float4*>(&g_BF[col4 * 4]);

    float4 o;
    o.x = p.x * p.x * a * b.x;
    o.y = p.y * p.y * a * b.y;
    o.z = p.z * p.z * a * b.z;
    o.w = p.w * p.w * a * b.w;
    reinterpret_cast<float4*>(C)[idx] = o;
}

// ---------------------------------------------------------------------------
// 21 x {iter, finalize} + C = 43 graph nodes. No sync/alloc/memcpy.
// cudaFuncSetAttribute is idempotent and capture-legal (not a stream op).
// ---------------------------------------------------------------------------
extern "C" void kernel_launch(void* const* d_in, const int* in_sizes, int n_in,
                              void* d_out, int out_size)
{
    const float* AT = (const float*)d_in[0];   // [4096]
    const float* BT = (const float*)d_in[1];   // [4096]
    const float* P  = (const float*)d_in[2];   // [4096, 4096]
    float* C = (float*)d_out;                  // [4096, 4096]

    cudaFuncSetAttribute(iter_kernel,
                         cudaFuncAttributeMaxDynamicSharedMemorySize, SMEM_IT);

    for (int it = 0; it < NITER; it++) {
        iter_kernel<<<NBLK_IT, NTHR, SMEM_IT>>>(P, AT, BT, it == 0 ? 1 : 0);
        finalize_bf_kernel<<<N / 2 / 256, 256>>>(BT);
    }
    compute_c_kernel<<<((size_t)N * (N / 4)) / 256, 256>>>(P, C);
}